// round 9
// baseline (speedup 1.0000x reference)
#include <cuda_runtime.h>
#include <cuda_bf16.h>
#include <cuda_fp16.h>
#include <cstdint>

#define Bn 2048
#define Dk 1024
#define Mn 16384
#define EPSF 1e-6f

#define BM 128
#define BN 128
#define BK 64
#define NCH (Dk / BK)        // 16 chunks

// padded pitches (bytes): A row = 64 bf16 = 128B -> 144; B row = 128 bf16 = 256B -> 272
#define A_PITCH 144
#define B_PITCH 272
#define A_HI 0
#define B_HI 18432           // 128*144
#define STAGE_SZ 35840       // + 64*272
#define NSTAGE 3
#define DOT_PITCH 136        // halves per smem dot row (272B, 16B-aligned)
#define DYN_BYTES (NSTAGE * STAGE_SZ)   // 107520 >= 128*136*2

#define DSLICE 8
#define E_MARGIN 3.5f
#define CAND_CAP (1 << 20)

// ---------------- device scratch ----------------
__device__ float g_rowconst[Bn];
__device__ float g_colconst[Mn];
__device__ float g_colpart[DSLICE * Mn];
__device__ unsigned long long g_best[Bn];    // approx (pass 1)
__device__ unsigned long long g_best2[Bn];   // exact (pass 3)
__device__ __nv_bfloat16 g_xhi[Bn * Dk];
__device__ __nv_bfloat16 g_whi[(size_t)Dk * Mn];
__device__ __half g_dot[(size_t)Bn * Mn];
__device__ int2 g_cand[CAND_CAP];
__device__ int g_ncand;

// ---------------- helpers ----------------
__device__ __forceinline__ uint32_t smem_u32(const void* p) {
    uint32_t a;
    asm("{ .reg .u64 t; cvta.to.shared.u64 t, %1; cvt.u32.u64 %0, t; }" : "=r"(a) : "l"(p));
    return a;
}
__device__ __forceinline__ void cp16(uint32_t s, const void* g) {
    asm volatile("cp.async.cg.shared.global [%0], [%1], 16;" :: "r"(s), "l"(g) : "memory");
}
__device__ __forceinline__ void cp_commit() { asm volatile("cp.async.commit_group;" ::: "memory"); }
__device__ __forceinline__ void cp_wait1()  { asm volatile("cp.async.wait_group 1;" ::: "memory"); }

__device__ __forceinline__ void ldsm_x4(uint32_t* r, uint32_t addr) {
    asm volatile("ldmatrix.sync.aligned.m8n8.x4.shared.b16 {%0,%1,%2,%3}, [%4];"
                 : "=r"(r[0]), "=r"(r[1]), "=r"(r[2]), "=r"(r[3]) : "r"(addr));
}
__device__ __forceinline__ void ldsm_x4_t(uint32_t* r, uint32_t addr) {
    asm volatile("ldmatrix.sync.aligned.m8n8.x4.trans.shared.b16 {%0,%1,%2,%3}, [%4];"
                 : "=r"(r[0]), "=r"(r[1]), "=r"(r[2]), "=r"(r[3]) : "r"(addr));
}
__device__ __forceinline__ void mma_bf16(float* c, const uint32_t* a, const uint32_t* b) {
    asm volatile(
        "mma.sync.aligned.m16n8k16.row.col.f32.bf16.bf16.f32 "
        "{%0,%1,%2,%3}, {%4,%5,%6,%7}, {%8,%9}, {%0,%1,%2,%3};"
        : "+f"(c[0]), "+f"(c[1]), "+f"(c[2]), "+f"(c[3])
        : "r"(a[0]), "r"(a[1]), "r"(a[2]), "r"(a[3]), "r"(b[0]), "r"(b[1]));
}

// ---------------- w convert + partial stats (float4 across m) ----------------
__global__ void som_wconv(const float* __restrict__ w) {
    int m4 = blockIdx.x * blockDim.x + threadIdx.x;    // 0..Mn/4-1
    int z = blockIdx.y;
    int d0 = z * (Dk / DSLICE);
    int m = m4 * 4;
    float4 s2 = make_float4(0.f, 0.f, 0.f, 0.f);
    float4 s1 = make_float4(0.f, 0.f, 0.f, 0.f);
#pragma unroll 4
    for (int i = 0; i < Dk / DSLICE; i++) {
        size_t idx = (size_t)(d0 + i) * Mn + m;
        float4 v = *(const float4*)(w + idx);
        s2.x = fmaf(v.x, v.x, s2.x); s1.x += v.x;
        s2.y = fmaf(v.y, v.y, s2.y); s1.y += v.y;
        s2.z = fmaf(v.z, v.z, s2.z); s1.z += v.z;
        s2.w = fmaf(v.w, v.w, s2.w); s1.w += v.w;
        __nv_bfloat16 h[4] = {__float2bfloat16(v.x), __float2bfloat16(v.y),
                              __float2bfloat16(v.z), __float2bfloat16(v.w)};
        *(uint2*)&g_whi[idx] = *(uint2*)h;
    }
    float4 r;
    r.x = s2.x - 2.0f * EPSF * s1.x;
    r.y = s2.y - 2.0f * EPSF * s1.y;
    r.z = s2.z - 2.0f * EPSF * s1.z;
    r.w = s2.w - 2.0f * EPSF * s1.w;
    *(float4*)&g_colpart[z * Mn + m] = r;
}

// colconst reduce + init best keys + candidate counter (merged)
__global__ void som_colreduce() {
    int m = blockIdx.x * blockDim.x + threadIdx.x;
    float s = 0.f;
#pragma unroll
    for (int z = 0; z < DSLICE; z++) s += g_colpart[z * Mn + m];
    g_colconst[m] = s;
    if (m < Bn) { g_best[m] = ~0ull; g_best2[m] = ~0ull; }
    if (m == 0) g_ncand = 0;
}

// ---------------- x convert + stats ----------------
__global__ void som_xconv(const float* __restrict__ x) {
    int gw = (blockIdx.x * blockDim.x + threadIdx.x) >> 5;
    int lane = threadIdx.x & 31;
    if (gw >= Bn) return;
    const float4* xr = (const float4*)(x + (size_t)gw * Dk);
    float s2 = 0.f, s1 = 0.f;
#pragma unroll
    for (int i = lane; i < Dk / 4; i += 32) {
        float4 v = xr[i];
        s1 += v.x + v.y + v.z + v.w;
        s2 = fmaf(v.x, v.x, s2); s2 = fmaf(v.y, v.y, s2);
        s2 = fmaf(v.z, v.z, s2); s2 = fmaf(v.w, v.w, s2);
        __nv_bfloat16 h[4] = {__float2bfloat16(v.x), __float2bfloat16(v.y),
                              __float2bfloat16(v.z), __float2bfloat16(v.w)};
        *(uint2*)&g_xhi[(size_t)gw * Dk + i * 4] = *(uint2*)h;
    }
#pragma unroll
    for (int o = 16; o; o >>= 1) {
        s1 += __shfl_down_sync(0xFFFFFFFFu, s1, o);
        s2 += __shfl_down_sync(0xFFFFFFFFu, s2, o);
    }
    if (lane == 0) g_rowconst[gw] = s2 + 2.0f * EPSF * s1 + (float)Dk * EPSF * EPSF;
}

// ---------------- pass 1: hi*hi GEMM + approx min + fp16 dot store ----------------
__global__ __launch_bounds__(256, 2) void som_mma(void) {
    extern __shared__ uint8_t dyn[];

    const int tid = threadIdx.x;
    const int lid = tid & 31;
    const int wid = tid >> 5;
    const int warp_m = wid >> 2;
    const int warp_n = wid & 3;
    const int bRow = blockIdx.x * BM;
    const int bCol = blockIdx.y * BN;

    float acc[4][4][4];
#pragma unroll
    for (int i = 0; i < 4; i++)
#pragma unroll
        for (int j = 0; j < 4; j++)
#pragma unroll
            for (int k = 0; k < 4; k++) acc[i][j][k] = 0.f;

    const uint32_t sb0 = smem_u32(dyn);

    // cp.async mapping, 4 x 16B each for A and B per stage per thread
    uint32_t a_soff[4], b_soff[4];
    size_t a_goff[4], b_goff[4];
#pragma unroll
    for (int i = 0; i < 4; i++) {
        int q = tid + i * 256;                 // 0..1023
        int ar = q >> 3, ak = q & 7;           // A: 128 rows x 8 chunks
        a_soff[i] = ar * A_PITCH + ak * 16;
        a_goff[i] = (size_t)(bRow + ar) * Dk + ak * 8;
        int br = q >> 4, bn = q & 15;          // B: 64 rows x 16 chunks
        b_soff[i] = br * B_PITCH + bn * 16;
        b_goff[i] = (size_t)br * Mn + bCol + bn * 8;
    }

    auto issue_stage = [&](int c) {
        const uint32_t sb = sb0 + (c % NSTAGE) * STAGE_SZ;
        const int k0 = c * BK;
#pragma unroll
        for (int i = 0; i < 4; i++) {
            cp16(sb + A_HI + a_soff[i], g_xhi + a_goff[i] + k0);
            cp16(sb + B_HI + b_soff[i], g_whi + b_goff[i] + (size_t)k0 * Mn);
        }
    };

    const uint32_t a_ld = (warp_m * 64 + (lid & 15)) * A_PITCH + (lid >> 4) * 16;
    const uint32_t b_ld = (((lid >> 3) & 1) * 8 + (lid & 7)) * B_PITCH +
                          warp_n * 64 + ((lid >> 3) >> 1) * 16;

    issue_stage(0); cp_commit();
    issue_stage(1); cp_commit();

#pragma unroll 1
    for (int c = 0; c < NCH; c++) {
        cp_wait1();
        __syncthreads();
        const uint32_t sb = sb0 + (c % NSTAGE) * STAGE_SZ;

        // issue the NEXT stage first: its buffer ((c+2)%3 == (c-1)%3) is dead
        // after the barrier above, and the copy now overlaps this whole chunk.
        if (c + 2 < NCH) issue_stage(c + 2);
        cp_commit();

#pragma unroll
        for (int ks = 0; ks < 4; ks++) {
            uint32_t bh[2][4], af[4][4];
#pragma unroll
            for (int g = 0; g < 2; g++)
                ldsm_x4_t(bh[g], sb + B_HI + b_ld + ks * 16 * B_PITCH + g * 32);
#pragma unroll
            for (int mt = 0; mt < 4; mt++)
                ldsm_x4(af[mt], sb + A_HI + a_ld + mt * 16 * A_PITCH + ks * 32);
#pragma unroll
            for (int mt = 0; mt < 4; mt++)
#pragma unroll
                for (int nt = 0; nt < 4; nt++)
                    mma_bf16(acc[mt][nt], af[mt], &bh[nt >> 1][(nt & 1) * 2]);
        }
    }

    // ---- epilogue ----
    float ccv[4][2];
    const int cbase = bCol + warp_n * 32 + (lid & 3) * 2;
#pragma unroll
    for (int nt = 0; nt < 4; nt++) {
        ccv[nt][0] = __ldg(&g_colconst[cbase + nt * 8]);
        ccv[nt][1] = __ldg(&g_colconst[cbase + nt * 8 + 1]);
    }

    __syncthreads();   // stage buffers dead; reuse as fp16 dot tile [128][DOT_PITCH]
    __half* sdot = (__half*)dyn;

#pragma unroll
    for (int mt = 0; mt < 4; mt++) {
#pragma unroll
        for (int half = 0; half < 2; half++) {
            const int rloc = warp_m * 64 + mt * 16 + (lid >> 2) + half * 8;
            const int row = bRow + rloc;
            const float rc = __ldg(&g_rowconst[row]);
            unsigned long long best = ~0ull;
#pragma unroll
            for (int nt = 0; nt < 4; nt++) {
                __half2 hp;
#pragma unroll
                for (int q = 0; q < 2; q++) {
                    float dotf = acc[mt][nt][half * 2 + q];
                    __half dh = __float2half(dotf);
                    ((__half*)&hp)[q] = dh;
                    float sq = fmaxf(rc + ccv[nt][q] - 2.0f * __half2float(dh), 0.0f);
                    int m = cbase + nt * 8 + q;
                    unsigned long long key =
                        ((unsigned long long)__float_as_uint(sq) << 32) | (unsigned int)m;
                    best = (key < best) ? key : best;
                }
                *(__half2*)&sdot[rloc * DOT_PITCH + warp_n * 32 + nt * 8 + (lid & 3) * 2] = hp;
            }
            unsigned long long o1 = __shfl_xor_sync(0xFFFFFFFFu, best, 1);
            best = (o1 < best) ? o1 : best;
            unsigned long long o2 = __shfl_xor_sync(0xFFFFFFFFu, best, 2);
            best = (o2 < best) ? o2 : best;
            if ((lid & 3) == 0) atomicMin(&g_best[row], best);
        }
    }

    __syncthreads();
    // coalesced store of the 128x128 fp16 tile to g_dot
#pragma unroll
    for (int i = 0; i < 8; i++) {
        int chunk = tid + i * 256;        // 0..2047
        int r = chunk >> 4;
        int o = (chunk & 15) * 8;
        uint4 v = *(uint4*)&sdot[r * DOT_PITCH + o];
        *(uint4*)&g_dot[(size_t)(bRow + r) * Mn + bCol + o] = v;
    }
}

// ---------------- pass 2: candidate scan (8 halves / thread, grid-stride) ----------------
__global__ void som_scan(void) {
    int t = blockIdx.x * blockDim.x + threadIdx.x;   // 0 .. Mn/8-1
    int b = blockIdx.y;
    int m0 = t * 8;
    float thresh = __uint_as_float((unsigned int)(g_best[b] >> 32)) + E_MARGIN;
    float rc = g_rowconst[b];
    uint4 dv = *(const uint4*)&g_dot[(size_t)b * Mn + m0];
    const __half2* dh = (const __half2*)&dv;
#pragma unroll
    for (int i = 0; i < 4; i++) {
        float2 d = __half22float2(dh[i]);
        float sq0 = fmaxf(rc + __ldg(&g_colconst[m0 + 2 * i])     - 2.0f * d.x, 0.0f);
        float sq1 = fmaxf(rc + __ldg(&g_colconst[m0 + 2 * i + 1]) - 2.0f * d.y, 0.0f);
        if (sq0 < thresh) {
            int idx = atomicAdd(&g_ncand, 1);
            if (idx < CAND_CAP) g_cand[idx] = make_int2(b, m0 + 2 * i);
        }
        if (sq1 < thresh) {
            int idx = atomicAdd(&g_ncand, 1);
            if (idx < CAND_CAP) g_cand[idx] = make_int2(b, m0 + 2 * i + 1);
        }
    }
}

// ---------------- pass 3: exact fp32 rescore ----------------
__global__ void som_rescore(const float* __restrict__ x, const float* __restrict__ w) {
    int gwarp = (blockIdx.x * blockDim.x + threadIdx.x) >> 5;
    int lane = threadIdx.x & 31;
    int nwarps = (gridDim.x * blockDim.x) >> 5;
    int n = g_ncand;
    if (n > CAND_CAP) n = CAND_CAP;
    for (int i = gwarp; i < n; i += nwarps) {
        int b = g_cand[i].x, m = g_cand[i].y;
        const float* xr = x + (size_t)b * Dk;
        float dot = 0.f;
#pragma unroll 4
        for (int k = lane; k < Dk; k += 32)
            dot = fmaf(xr[k], __ldg(&w[(size_t)k * Mn + m]), dot);
#pragma unroll
        for (int o = 16; o; o >>= 1) dot += __shfl_down_sync(0xFFFFFFFFu, dot, o);
        if (lane == 0) {
            float sq = fmaxf(g_rowconst[b] + g_colconst[m] - 2.0f * dot, 0.0f);
            unsigned long long key =
                ((unsigned long long)__float_as_uint(sq) << 32) | (unsigned int)m;
            atomicMin(&g_best2[b], key);
        }
    }
}

// ---------------- finalize ----------------
__global__ void som_finalize(const float* __restrict__ loc, float* __restrict__ out) {
    __shared__ float ssum[256];
    int tid = threadIdx.x;
    float local = 0.f;
    for (int b = tid; b < Bn; b += 256) {
        unsigned long long v = g_best2[b];
        unsigned int m = (unsigned int)(v & 0xFFFFFFFFu);
        float sq = __uint_as_float((unsigned int)(v >> 32));
        out[b] = (float)m;
        out[Bn + 2 * b + 0] = loc[2 * m + 0];
        out[Bn + 2 * b + 1] = loc[2 * m + 1];
        local += sqrtf(sq);
    }
    ssum[tid] = local;
    __syncthreads();
    for (int s = 128; s; s >>= 1) {
        if (tid < s) ssum[tid] += ssum[tid + s];
        __syncthreads();
    }
    if (tid == 0) out[3 * Bn] = ssum[0] / (float)Bn;
}

// ---------------- launch ----------------
extern "C" void kernel_launch(void* const* d_in, const int* in_sizes, int n_in,
                              void* d_out, int out_size) {
    const float* x = (const float*)d_in[0];   // [B, D]
    const float* w = (const float*)d_in[1];   // [D, M]
    const float* loc = (const float*)d_in[2]; // [M, 2]
    float* out = (float*)d_out;

    static int configured = 0;
    if (!configured) {
        cudaFuncSetAttribute(som_mma, cudaFuncAttributeMaxDynamicSharedMemorySize, DYN_BYTES);
        configured = 1;
    }

    som_wconv<<<dim3(Mn / 4 / 256, DSLICE), 256>>>(w);
    som_xconv<<<Bn * 32 / 256, 256>>>(x);
    som_colreduce<<<Mn / 256, 256>>>();

    dim3 grid(Bn / BM, Mn / BN);   // x fastest: consecutive CTAs share the w panel (L2 reuse)
    som_mma<<<grid, 256, DYN_BYTES>>>();

    som_scan<<<dim3(Mn / 8 / 256, Bn), 256>>>();
    som_rescore<<<256, 256>>>(x, w);

    som_finalize<<<1, 256>>>(loc, out);
}

// round 10
// speedup vs baseline: 1.0002x; 1.0002x over previous
#include <cuda_runtime.h>
#include <cuda_bf16.h>
#include <cuda_fp16.h>
#include <cstdint>

#define Bn 2048
#define Dk 1024
#define Mn 16384
#define EPSF 1e-6f

#define BM 128
#define BN 128
#define BK 64
#define NCH (Dk / BK)        // 16 chunks

// padded pitches (bytes): A row = 64 bf16 = 128B -> 144; B row = 128 bf16 = 256B -> 272
#define A_PITCH 144
#define B_PITCH 272
#define A_HI 0
#define B_HI 18432           // 128*144
#define STAGE_SZ 35840       // + 64*272
#define NSTAGE 3
#define DOT_PITCH 136        // halves per smem dot row (272B, 16B-aligned)
#define DYN_BYTES (NSTAGE * STAGE_SZ)   // 107520 >= 128*136*2

#define DSLICE 8
#define E_MARGIN 3.5f
#define CAND_CAP (1 << 20)

// ---------------- device scratch ----------------
__device__ float g_rowconst[Bn];
__device__ float g_colconst[Mn];
__device__ float g_colpart[DSLICE * Mn];
__device__ unsigned long long g_best[Bn];    // approx (pass 1)
__device__ unsigned long long g_best2[Bn];   // exact (pass 3)
__device__ __nv_bfloat16 g_xhi[Bn * Dk];
__device__ __nv_bfloat16 g_whi[(size_t)Dk * Mn];
__device__ __half g_dot[(size_t)Bn * Mn];
__device__ int2 g_cand[CAND_CAP];
__device__ int g_ncand;

// ---------------- helpers ----------------
__device__ __forceinline__ uint32_t smem_u32(const void* p) {
    uint32_t a;
    asm("{ .reg .u64 t; cvta.to.shared.u64 t, %1; cvt.u32.u64 %0, t; }" : "=r"(a) : "l"(p));
    return a;
}
__device__ __forceinline__ void cp16(uint32_t s, const void* g) {
    asm volatile("cp.async.cg.shared.global [%0], [%1], 16;" :: "r"(s), "l"(g) : "memory");
}
__device__ __forceinline__ void cp_commit() { asm volatile("cp.async.commit_group;" ::: "memory"); }
__device__ __forceinline__ void cp_wait1()  { asm volatile("cp.async.wait_group 1;" ::: "memory"); }

__device__ __forceinline__ void ldsm_x4(uint32_t* r, uint32_t addr) {
    asm volatile("ldmatrix.sync.aligned.m8n8.x4.shared.b16 {%0,%1,%2,%3}, [%4];"
                 : "=r"(r[0]), "=r"(r[1]), "=r"(r[2]), "=r"(r[3]) : "r"(addr));
}
__device__ __forceinline__ void ldsm_x4_t(uint32_t* r, uint32_t addr) {
    asm volatile("ldmatrix.sync.aligned.m8n8.x4.trans.shared.b16 {%0,%1,%2,%3}, [%4];"
                 : "=r"(r[0]), "=r"(r[1]), "=r"(r[2]), "=r"(r[3]) : "r"(addr));
}
__device__ __forceinline__ void mma_bf16(float* c, const uint32_t* a, const uint32_t* b) {
    asm volatile(
        "mma.sync.aligned.m16n8k16.row.col.f32.bf16.bf16.f32 "
        "{%0,%1,%2,%3}, {%4,%5,%6,%7}, {%8,%9}, {%0,%1,%2,%3};"
        : "+f"(c[0]), "+f"(c[1]), "+f"(c[2]), "+f"(c[3])
        : "r"(a[0]), "r"(a[1]), "r"(a[2]), "r"(a[3]), "r"(b[0]), "r"(b[1]));
}

// ---------------- w convert + partial stats (float4 across m) ----------------
__global__ void som_wconv(const float* __restrict__ w) {
    int m4 = blockIdx.x * blockDim.x + threadIdx.x;    // 0..Mn/4-1
    int z = blockIdx.y;
    int d0 = z * (Dk / DSLICE);
    int m = m4 * 4;
    float4 s2 = make_float4(0.f, 0.f, 0.f, 0.f);
    float4 s1 = make_float4(0.f, 0.f, 0.f, 0.f);
#pragma unroll 4
    for (int i = 0; i < Dk / DSLICE; i++) {
        size_t idx = (size_t)(d0 + i) * Mn + m;
        float4 v = *(const float4*)(w + idx);
        s2.x = fmaf(v.x, v.x, s2.x); s1.x += v.x;
        s2.y = fmaf(v.y, v.y, s2.y); s1.y += v.y;
        s2.z = fmaf(v.z, v.z, s2.z); s1.z += v.z;
        s2.w = fmaf(v.w, v.w, s2.w); s1.w += v.w;
        __nv_bfloat16 h[4] = {__float2bfloat16(v.x), __float2bfloat16(v.y),
                              __float2bfloat16(v.z), __float2bfloat16(v.w)};
        *(uint2*)&g_whi[idx] = *(uint2*)h;
    }
    float4 r;
    r.x = s2.x - 2.0f * EPSF * s1.x;
    r.y = s2.y - 2.0f * EPSF * s1.y;
    r.z = s2.z - 2.0f * EPSF * s1.z;
    r.w = s2.w - 2.0f * EPSF * s1.w;
    *(float4*)&g_colpart[z * Mn + m] = r;
}

// colconst reduce + init best keys + candidate counter (merged)
__global__ void som_colreduce() {
    int m = blockIdx.x * blockDim.x + threadIdx.x;
    float s = 0.f;
#pragma unroll
    for (int z = 0; z < DSLICE; z++) s += g_colpart[z * Mn + m];
    g_colconst[m] = s;
    if (m < Bn) { g_best[m] = ~0ull; g_best2[m] = ~0ull; }
    if (m == 0) g_ncand = 0;
}

// ---------------- x convert + stats ----------------
__global__ void som_xconv(const float* __restrict__ x) {
    int gw = (blockIdx.x * blockDim.x + threadIdx.x) >> 5;
    int lane = threadIdx.x & 31;
    if (gw >= Bn) return;
    const float4* xr = (const float4*)(x + (size_t)gw * Dk);
    float s2 = 0.f, s1 = 0.f;
#pragma unroll
    for (int i = lane; i < Dk / 4; i += 32) {
        float4 v = xr[i];
        s1 += v.x + v.y + v.z + v.w;
        s2 = fmaf(v.x, v.x, s2); s2 = fmaf(v.y, v.y, s2);
        s2 = fmaf(v.z, v.z, s2); s2 = fmaf(v.w, v.w, s2);
        __nv_bfloat16 h[4] = {__float2bfloat16(v.x), __float2bfloat16(v.y),
                              __float2bfloat16(v.z), __float2bfloat16(v.w)};
        *(uint2*)&g_xhi[(size_t)gw * Dk + i * 4] = *(uint2*)h;
    }
#pragma unroll
    for (int o = 16; o; o >>= 1) {
        s1 += __shfl_down_sync(0xFFFFFFFFu, s1, o);
        s2 += __shfl_down_sync(0xFFFFFFFFu, s2, o);
    }
    if (lane == 0) g_rowconst[gw] = s2 + 2.0f * EPSF * s1 + (float)Dk * EPSF * EPSF;
}

// ---------------- pass 1: hi*hi GEMM + approx min + fp16 dot store ----------------
__global__ __launch_bounds__(256, 2) void som_mma(void) {
    extern __shared__ uint8_t dyn[];

    const int tid = threadIdx.x;
    const int lid = tid & 31;
    const int wid = tid >> 5;
    const int warp_m = wid >> 2;
    const int warp_n = wid & 3;
    const int bRow = blockIdx.x * BM;
    const int bCol = blockIdx.y * BN;

    float acc[4][4][4];
#pragma unroll
    for (int i = 0; i < 4; i++)
#pragma unroll
        for (int j = 0; j < 4; j++)
#pragma unroll
            for (int k = 0; k < 4; k++) acc[i][j][k] = 0.f;

    const uint32_t sb0 = smem_u32(dyn);

    // cp.async mapping, 4 x 16B each for A and B per stage per thread
    uint32_t a_soff[4], b_soff[4];
    size_t a_goff[4], b_goff[4];
#pragma unroll
    for (int i = 0; i < 4; i++) {
        int q = tid + i * 256;                 // 0..1023
        int ar = q >> 3, ak = q & 7;           // A: 128 rows x 8 chunks
        a_soff[i] = ar * A_PITCH + ak * 16;
        a_goff[i] = (size_t)(bRow + ar) * Dk + ak * 8;
        int br = q >> 4, bn = q & 15;          // B: 64 rows x 16 chunks
        b_soff[i] = br * B_PITCH + bn * 16;
        b_goff[i] = (size_t)br * Mn + bCol + bn * 8;
    }

    auto issue_stage = [&](int c) {
        const uint32_t sb = sb0 + (c % NSTAGE) * STAGE_SZ;
        const int k0 = c * BK;
#pragma unroll
        for (int i = 0; i < 4; i++) {
            cp16(sb + A_HI + a_soff[i], g_xhi + a_goff[i] + k0);
            cp16(sb + B_HI + b_soff[i], g_whi + b_goff[i] + (size_t)k0 * Mn);
        }
    };

    const uint32_t a_ld = (warp_m * 64 + (lid & 15)) * A_PITCH + (lid >> 4) * 16;
    const uint32_t b_ld = (((lid >> 3) & 1) * 8 + (lid & 7)) * B_PITCH +
                          warp_n * 64 + ((lid >> 3) >> 1) * 16;

    issue_stage(0); cp_commit();
    issue_stage(1); cp_commit();

#pragma unroll 1
    for (int c = 0; c < NCH; c++) {
        cp_wait1();
        __syncthreads();
        const uint32_t sb = sb0 + (c % NSTAGE) * STAGE_SZ;

        // issue the NEXT stage first: its buffer ((c+2)%3 == (c-1)%3) is dead
        // after the barrier above, and the copy now overlaps this whole chunk.
        if (c + 2 < NCH) issue_stage(c + 2);
        cp_commit();

#pragma unroll
        for (int ks = 0; ks < 4; ks++) {
            uint32_t bh[2][4], af[4][4];
#pragma unroll
            for (int g = 0; g < 2; g++)
                ldsm_x4_t(bh[g], sb + B_HI + b_ld + ks * 16 * B_PITCH + g * 32);
#pragma unroll
            for (int mt = 0; mt < 4; mt++)
                ldsm_x4(af[mt], sb + A_HI + a_ld + mt * 16 * A_PITCH + ks * 32);
#pragma unroll
            for (int mt = 0; mt < 4; mt++)
#pragma unroll
                for (int nt = 0; nt < 4; nt++)
                    mma_bf16(acc[mt][nt], af[mt], &bh[nt >> 1][(nt & 1) * 2]);
        }
    }

    // ---- epilogue ----
    float ccv[4][2];
    const int cbase = bCol + warp_n * 32 + (lid & 3) * 2;
#pragma unroll
    for (int nt = 0; nt < 4; nt++) {
        ccv[nt][0] = __ldg(&g_colconst[cbase + nt * 8]);
        ccv[nt][1] = __ldg(&g_colconst[cbase + nt * 8 + 1]);
    }

    __syncthreads();   // stage buffers dead; reuse as fp16 dot tile [128][DOT_PITCH]
    __half* sdot = (__half*)dyn;

#pragma unroll
    for (int mt = 0; mt < 4; mt++) {
#pragma unroll
        for (int half = 0; half < 2; half++) {
            const int rloc = warp_m * 64 + mt * 16 + (lid >> 2) + half * 8;
            const int row = bRow + rloc;
            const float rc = __ldg(&g_rowconst[row]);
            unsigned long long best = ~0ull;
#pragma unroll
            for (int nt = 0; nt < 4; nt++) {
                __half2 hp;
#pragma unroll
                for (int q = 0; q < 2; q++) {
                    float dotf = acc[mt][nt][half * 2 + q];
                    __half dh = __float2half(dotf);
                    ((__half*)&hp)[q] = dh;
                    float sq = fmaxf(rc + ccv[nt][q] - 2.0f * __half2float(dh), 0.0f);
                    int m = cbase + nt * 8 + q;
                    unsigned long long key =
                        ((unsigned long long)__float_as_uint(sq) << 32) | (unsigned int)m;
                    best = (key < best) ? key : best;
                }
                *(__half2*)&sdot[rloc * DOT_PITCH + warp_n * 32 + nt * 8 + (lid & 3) * 2] = hp;
            }
            unsigned long long o1 = __shfl_xor_sync(0xFFFFFFFFu, best, 1);
            best = (o1 < best) ? o1 : best;
            unsigned long long o2 = __shfl_xor_sync(0xFFFFFFFFu, best, 2);
            best = (o2 < best) ? o2 : best;
            if ((lid & 3) == 0) atomicMin(&g_best[row], best);
        }
    }

    __syncthreads();
    // coalesced store of the 128x128 fp16 tile to g_dot
#pragma unroll
    for (int i = 0; i < 8; i++) {
        int chunk = tid + i * 256;        // 0..2047
        int r = chunk >> 4;
        int o = (chunk & 15) * 8;
        uint4 v = *(uint4*)&sdot[r * DOT_PITCH + o];
        *(uint4*)&g_dot[(size_t)(bRow + r) * Mn + bCol + o] = v;
    }
}

// ---------------- pass 2: candidate scan (8 halves / thread, grid-stride) ----------------
__global__ void som_scan(void) {
    int t = blockIdx.x * blockDim.x + threadIdx.x;   // 0 .. Mn/8-1
    int b = blockIdx.y;
    int m0 = t * 8;
    float thresh = __uint_as_float((unsigned int)(g_best[b] >> 32)) + E_MARGIN;
    float rc = g_rowconst[b];
    uint4 dv = *(const uint4*)&g_dot[(size_t)b * Mn + m0];
    const __half2* dh = (const __half2*)&dv;
#pragma unroll
    for (int i = 0; i < 4; i++) {
        float2 d = __half22float2(dh[i]);
        float sq0 = fmaxf(rc + __ldg(&g_colconst[m0 + 2 * i])     - 2.0f * d.x, 0.0f);
        float sq1 = fmaxf(rc + __ldg(&g_colconst[m0 + 2 * i + 1]) - 2.0f * d.y, 0.0f);
        if (sq0 < thresh) {
            int idx = atomicAdd(&g_ncand, 1);
            if (idx < CAND_CAP) g_cand[idx] = make_int2(b, m0 + 2 * i);
        }
        if (sq1 < thresh) {
            int idx = atomicAdd(&g_ncand, 1);
            if (idx < CAND_CAP) g_cand[idx] = make_int2(b, m0 + 2 * i + 1);
        }
    }
}

// ---------------- pass 3: exact fp32 rescore ----------------
__global__ void som_rescore(const float* __restrict__ x, const float* __restrict__ w) {
    int gwarp = (blockIdx.x * blockDim.x + threadIdx.x) >> 5;
    int lane = threadIdx.x & 31;
    int nwarps = (gridDim.x * blockDim.x) >> 5;
    int n = g_ncand;
    if (n > CAND_CAP) n = CAND_CAP;
    for (int i = gwarp; i < n; i += nwarps) {
        int b = g_cand[i].x, m = g_cand[i].y;
        const float* xr = x + (size_t)b * Dk;
        float dot = 0.f;
#pragma unroll 4
        for (int k = lane; k < Dk; k += 32)
            dot = fmaf(xr[k], __ldg(&w[(size_t)k * Mn + m]), dot);
#pragma unroll
        for (int o = 16; o; o >>= 1) dot += __shfl_down_sync(0xFFFFFFFFu, dot, o);
        if (lane == 0) {
            float sq = fmaxf(g_rowconst[b] + g_colconst[m] - 2.0f * dot, 0.0f);
            unsigned long long key =
                ((unsigned long long)__float_as_uint(sq) << 32) | (unsigned int)m;
            atomicMin(&g_best2[b], key);
        }
    }
}

// ---------------- finalize ----------------
__global__ void som_finalize(const float* __restrict__ loc, float* __restrict__ out) {
    __shared__ float ssum[256];
    int tid = threadIdx.x;
    float local = 0.f;
    for (int b = tid; b < Bn; b += 256) {
        unsigned long long v = g_best2[b];
        unsigned int m = (unsigned int)(v & 0xFFFFFFFFu);
        float sq = __uint_as_float((unsigned int)(v >> 32));
        out[b] = (float)m;
        out[Bn + 2 * b + 0] = loc[2 * m + 0];
        out[Bn + 2 * b + 1] = loc[2 * m + 1];
        local += sqrtf(sq);
    }
    ssum[tid] = local;
    __syncthreads();
    for (int s = 128; s; s >>= 1) {
        if (tid < s) ssum[tid] += ssum[tid + s];
        __syncthreads();
    }
    if (tid == 0) out[3 * Bn] = ssum[0] / (float)Bn;
}

// ---------------- launch ----------------
extern "C" void kernel_launch(void* const* d_in, const int* in_sizes, int n_in,
                              void* d_out, int out_size) {
    const float* x = (const float*)d_in[0];   // [B, D]
    const float* w = (const float*)d_in[1];   // [D, M]
    const float* loc = (const float*)d_in[2]; // [M, 2]
    float* out = (float*)d_out;

    static int configured = 0;
    if (!configured) {
        cudaFuncSetAttribute(som_mma, cudaFuncAttributeMaxDynamicSharedMemorySize, DYN_BYTES);
        configured = 1;
    }

    som_wconv<<<dim3(Mn / 4 / 256, DSLICE), 256>>>(w);
    som_xconv<<<Bn * 32 / 256, 256>>>(x);
    som_colreduce<<<Mn / 256, 256>>>();

    dim3 grid(Bn / BM, Mn / BN);   // x fastest: consecutive CTAs share the w panel (L2 reuse)
    som_mma<<<grid, 256, DYN_BYTES>>>();

    som_scan<<<dim3(Mn / 8 / 256, Bn), 256>>>();
    som_rescore<<<256, 256>>>(x, w);

    som_finalize<<<1, 256>>>(loc, out);
}

// round 11
// speedup vs baseline: 1.1009x; 1.1006x over previous
#include <cuda_runtime.h>
#include <cuda_bf16.h>
#include <cuda_fp16.h>
#include <cstdint>

#define Bn 2048
#define Dk 1024
#define Mn 16384
#define EPSF 1e-6f

#define BM 128
#define BN 128
#define BK 64
#define NCH (Dk / BK)        // 16 chunks
#define NTILE (Mn / BN)      // 128 M-tiles

// padded pitches (bytes): A row = 64 bf16 = 128B -> 144; B row = 128 bf16 = 256B -> 272
#define A_PITCH 144
#define B_PITCH 272
#define A_HI 0
#define B_HI 18432           // 128*144
#define STAGE_SZ 35840       // + 64*272
#define NSTAGE 3
#define DOT_PITCH 136        // halves per smem dot row (272B, 16B-aligned)
#define DYN_BYTES (NSTAGE * STAGE_SZ)   // 107520 >= 128*136*2

#define DSLICE 8
#define E_MARGIN 3.5f
#define CAND_CAP (1 << 20)

// ---------------- device scratch ----------------
__device__ float g_rowconst[Bn];
__device__ float g_colconst[Mn];
__device__ float g_colpart[DSLICE * Mn];
__device__ unsigned long long g_best[Bn];    // approx (pass 1)
__device__ unsigned long long g_best2[Bn];   // exact (pass 3)
__device__ float g_tilemin[Bn * NTILE];      // approx sq min per (row, tile)
__device__ __nv_bfloat16 g_xhi[Bn * Dk];
__device__ __nv_bfloat16 g_whi[(size_t)Dk * Mn];
__device__ __half g_dot[(size_t)Bn * Mn];
__device__ int2 g_cand[CAND_CAP];
__device__ int g_ncand;

// ---------------- helpers ----------------
__device__ __forceinline__ uint32_t smem_u32(const void* p) {
    uint32_t a;
    asm("{ .reg .u64 t; cvta.to.shared.u64 t, %1; cvt.u32.u64 %0, t; }" : "=r"(a) : "l"(p));
    return a;
}
__device__ __forceinline__ void cp16(uint32_t s, const void* g) {
    asm volatile("cp.async.cg.shared.global [%0], [%1], 16;" :: "r"(s), "l"(g) : "memory");
}
__device__ __forceinline__ void cp_commit() { asm volatile("cp.async.commit_group;" ::: "memory"); }
__device__ __forceinline__ void cp_wait1()  { asm volatile("cp.async.wait_group 1;" ::: "memory"); }

__device__ __forceinline__ void ldsm_x4(uint32_t* r, uint32_t addr) {
    asm volatile("ldmatrix.sync.aligned.m8n8.x4.shared.b16 {%0,%1,%2,%3}, [%4];"
                 : "=r"(r[0]), "=r"(r[1]), "=r"(r[2]), "=r"(r[3]) : "r"(addr));
}
__device__ __forceinline__ void ldsm_x4_t(uint32_t* r, uint32_t addr) {
    asm volatile("ldmatrix.sync.aligned.m8n8.x4.trans.shared.b16 {%0,%1,%2,%3}, [%4];"
                 : "=r"(r[0]), "=r"(r[1]), "=r"(r[2]), "=r"(r[3]) : "r"(addr));
}
__device__ __forceinline__ void mma_bf16(float* c, const uint32_t* a, const uint32_t* b) {
    asm volatile(
        "mma.sync.aligned.m16n8k16.row.col.f32.bf16.bf16.f32 "
        "{%0,%1,%2,%3}, {%4,%5,%6,%7}, {%8,%9}, {%0,%1,%2,%3};"
        : "+f"(c[0]), "+f"(c[1]), "+f"(c[2]), "+f"(c[3])
        : "r"(a[0]), "r"(a[1]), "r"(a[2]), "r"(a[3]), "r"(b[0]), "r"(b[1]));
}

// ---------------- w convert + partial stats (float4 across m) ----------------
__global__ void som_wconv(const float* __restrict__ w) {
    int m4 = blockIdx.x * blockDim.x + threadIdx.x;    // 0..Mn/4-1
    int z = blockIdx.y;
    int d0 = z * (Dk / DSLICE);
    int m = m4 * 4;
    float4 s2 = make_float4(0.f, 0.f, 0.f, 0.f);
    float4 s1 = make_float4(0.f, 0.f, 0.f, 0.f);
#pragma unroll 4
    for (int i = 0; i < Dk / DSLICE; i++) {
        size_t idx = (size_t)(d0 + i) * Mn + m;
        float4 v = *(const float4*)(w + idx);
        s2.x = fmaf(v.x, v.x, s2.x); s1.x += v.x;
        s2.y = fmaf(v.y, v.y, s2.y); s1.y += v.y;
        s2.z = fmaf(v.z, v.z, s2.z); s1.z += v.z;
        s2.w = fmaf(v.w, v.w, s2.w); s1.w += v.w;
        __nv_bfloat16 h[4] = {__float2bfloat16(v.x), __float2bfloat16(v.y),
                              __float2bfloat16(v.z), __float2bfloat16(v.w)};
        *(uint2*)&g_whi[idx] = *(uint2*)h;
    }
    float4 r;
    r.x = s2.x - 2.0f * EPSF * s1.x;
    r.y = s2.y - 2.0f * EPSF * s1.y;
    r.z = s2.z - 2.0f * EPSF * s1.z;
    r.w = s2.w - 2.0f * EPSF * s1.w;
    *(float4*)&g_colpart[z * Mn + m] = r;
}

// colconst reduce + init best keys + candidate counter (merged)
__global__ void som_colreduce() {
    int m = blockIdx.x * blockDim.x + threadIdx.x;
    float s = 0.f;
#pragma unroll
    for (int z = 0; z < DSLICE; z++) s += g_colpart[z * Mn + m];
    g_colconst[m] = s;
    if (m < Bn) { g_best[m] = ~0ull; g_best2[m] = ~0ull; }
    if (m == 0) g_ncand = 0;
}

// ---------------- x convert + stats ----------------
__global__ void som_xconv(const float* __restrict__ x) {
    int gw = (blockIdx.x * blockDim.x + threadIdx.x) >> 5;
    int lane = threadIdx.x & 31;
    if (gw >= Bn) return;
    const float4* xr = (const float4*)(x + (size_t)gw * Dk);
    float s2 = 0.f, s1 = 0.f;
#pragma unroll
    for (int i = lane; i < Dk / 4; i += 32) {
        float4 v = xr[i];
        s1 += v.x + v.y + v.z + v.w;
        s2 = fmaf(v.x, v.x, s2); s2 = fmaf(v.y, v.y, s2);
        s2 = fmaf(v.z, v.z, s2); s2 = fmaf(v.w, v.w, s2);
        __nv_bfloat16 h[4] = {__float2bfloat16(v.x), __float2bfloat16(v.y),
                              __float2bfloat16(v.z), __float2bfloat16(v.w)};
        *(uint2*)&g_xhi[(size_t)gw * Dk + i * 4] = *(uint2*)h;
    }
#pragma unroll
    for (int o = 16; o; o >>= 1) {
        s1 += __shfl_down_sync(0xFFFFFFFFu, s1, o);
        s2 += __shfl_down_sync(0xFFFFFFFFu, s2, o);
    }
    if (lane == 0) g_rowconst[gw] = s2 + 2.0f * EPSF * s1 + (float)Dk * EPSF * EPSF;
}

// ---------------- pass 1: hi*hi GEMM + approx min + fp16 dot store ----------------
__global__ __launch_bounds__(256, 2) void som_mma(void) {
    extern __shared__ uint8_t dyn[];
    __shared__ float s_tmin[128][4];

    const int tid = threadIdx.x;
    const int lid = tid & 31;
    const int wid = tid >> 5;
    const int warp_m = wid >> 2;
    const int warp_n = wid & 3;
    const int bRow = blockIdx.x * BM;
    const int bCol = blockIdx.y * BN;

    float acc[4][4][4];
#pragma unroll
    for (int i = 0; i < 4; i++)
#pragma unroll
        for (int j = 0; j < 4; j++)
#pragma unroll
            for (int k = 0; k < 4; k++) acc[i][j][k] = 0.f;

    const uint32_t sb0 = smem_u32(dyn);

    // cp.async mapping, 4 x 16B each for A and B per stage per thread
    uint32_t a_soff[4], b_soff[4];
    size_t a_goff[4], b_goff[4];
#pragma unroll
    for (int i = 0; i < 4; i++) {
        int q = tid + i * 256;                 // 0..1023
        int ar = q >> 3, ak = q & 7;           // A: 128 rows x 8 chunks
        a_soff[i] = ar * A_PITCH + ak * 16;
        a_goff[i] = (size_t)(bRow + ar) * Dk + ak * 8;
        int br = q >> 4, bn = q & 15;          // B: 64 rows x 16 chunks
        b_soff[i] = br * B_PITCH + bn * 16;
        b_goff[i] = (size_t)br * Mn + bCol + bn * 8;
    }

    auto issue_stage = [&](int c) {
        const uint32_t sb = sb0 + (c % NSTAGE) * STAGE_SZ;
        const int k0 = c * BK;
#pragma unroll
        for (int i = 0; i < 4; i++) {
            cp16(sb + A_HI + a_soff[i], g_xhi + a_goff[i] + k0);
            cp16(sb + B_HI + b_soff[i], g_whi + b_goff[i] + (size_t)k0 * Mn);
        }
    };

    const uint32_t a_ld = (warp_m * 64 + (lid & 15)) * A_PITCH + (lid >> 4) * 16;
    const uint32_t b_ld = (((lid >> 3) & 1) * 8 + (lid & 7)) * B_PITCH +
                          warp_n * 64 + ((lid >> 3) >> 1) * 16;

    issue_stage(0); cp_commit();
    issue_stage(1); cp_commit();

#pragma unroll 1
    for (int c = 0; c < NCH; c++) {
        cp_wait1();
        __syncthreads();
        const uint32_t sb = sb0 + (c % NSTAGE) * STAGE_SZ;

#pragma unroll
        for (int ks = 0; ks < 4; ks++) {
            uint32_t bh[2][4], af[4][4];
#pragma unroll
            for (int g = 0; g < 2; g++)
                ldsm_x4_t(bh[g], sb + B_HI + b_ld + ks * 16 * B_PITCH + g * 32);
#pragma unroll
            for (int mt = 0; mt < 4; mt++)
                ldsm_x4(af[mt], sb + A_HI + a_ld + mt * 16 * A_PITCH + ks * 32);
#pragma unroll
            for (int mt = 0; mt < 4; mt++)
#pragma unroll
                for (int nt = 0; nt < 4; nt++)
                    mma_bf16(acc[mt][nt], af[mt], &bh[nt >> 1][(nt & 1) * 2]);
        }

        if (c + 2 < NCH) issue_stage(c + 2);
        cp_commit();
    }

    // ---- epilogue ----
    float ccv[4][2];
    const int cbase = bCol + warp_n * 32 + (lid & 3) * 2;
#pragma unroll
    for (int nt = 0; nt < 4; nt++) {
        ccv[nt][0] = __ldg(&g_colconst[cbase + nt * 8]);
        ccv[nt][1] = __ldg(&g_colconst[cbase + nt * 8 + 1]);
    }

    __syncthreads();   // stage buffers dead; reuse as fp16 dot tile [128][DOT_PITCH]
    __half* sdot = (__half*)dyn;

#pragma unroll
    for (int mt = 0; mt < 4; mt++) {
#pragma unroll
        for (int half = 0; half < 2; half++) {
            const int rloc = warp_m * 64 + mt * 16 + (lid >> 2) + half * 8;
            const int row = bRow + rloc;
            const float rc = __ldg(&g_rowconst[row]);
            unsigned long long best = ~0ull;
#pragma unroll
            for (int nt = 0; nt < 4; nt++) {
                __half2 hp;
#pragma unroll
                for (int q = 0; q < 2; q++) {
                    float dotf = acc[mt][nt][half * 2 + q];
                    __half dh = __float2half(dotf);
                    ((__half*)&hp)[q] = dh;
                    float sq = fmaxf(rc + ccv[nt][q] - 2.0f * __half2float(dh), 0.0f);
                    int m = cbase + nt * 8 + q;
                    unsigned long long key =
                        ((unsigned long long)__float_as_uint(sq) << 32) | (unsigned int)m;
                    best = (key < best) ? key : best;
                }
                *(__half2*)&sdot[rloc * DOT_PITCH + warp_n * 32 + nt * 8 + (lid & 3) * 2] = hp;
            }
            unsigned long long o1 = __shfl_xor_sync(0xFFFFFFFFu, best, 1);
            best = (o1 < best) ? o1 : best;
            unsigned long long o2 = __shfl_xor_sync(0xFFFFFFFFu, best, 2);
            best = (o2 < best) ? o2 : best;
            if ((lid & 3) == 0) {
                s_tmin[rloc][warp_n] = __uint_as_float((unsigned int)(best >> 32));
                atomicMin(&g_best[row], best);
            }
        }
    }

    __syncthreads();
    // per-row tile min over the 4 warp_n columns -> g_tilemin
    if (tid < 128) {
        float t0 = fminf(s_tmin[tid][0], s_tmin[tid][1]);
        float t1 = fminf(s_tmin[tid][2], s_tmin[tid][3]);
        g_tilemin[(bRow + tid) * NTILE + blockIdx.y] = fminf(t0, t1);
    }
    // coalesced store of the 128x128 fp16 tile to g_dot
#pragma unroll
    for (int i = 0; i < 8; i++) {
        int chunk = tid + i * 256;        // 0..2047
        int r = chunk >> 4;
        int o = (chunk & 15) * 8;
        uint4 v = *(uint4*)&sdot[r * DOT_PITCH + o];
        *(uint4*)&g_dot[(size_t)(bRow + r) * Mn + bCol + o] = v;
    }
}

// ---------------- pass 2: tile-screened candidate scan ----------------
// one warp per (row, tile); skip tile unless its approx min beats thresh
__global__ void som_scan(void) {
    int gwarp = blockIdx.x * 8 + (threadIdx.x >> 5);   // 0 .. Bn*NTILE-1
    int lane = threadIdx.x & 31;
    int b = gwarp >> 7;          // / NTILE
    int tile = gwarp & (NTILE - 1);
    float thresh = __uint_as_float((unsigned int)(g_best[b] >> 32)) + E_MARGIN;
    if (g_tilemin[b * NTILE + tile] >= thresh) return;

    float rc = g_rowconst[b];
    int m0 = tile * BN + lane * 4;
    uint2 dv = *(const uint2*)&g_dot[(size_t)b * Mn + m0];
    const __half2* dh = (const __half2*)&dv;
#pragma unroll
    for (int i = 0; i < 2; i++) {
        float2 d = __half22float2(dh[i]);
        float sq0 = fmaxf(rc + __ldg(&g_colconst[m0 + 2 * i])     - 2.0f * d.x, 0.0f);
        float sq1 = fmaxf(rc + __ldg(&g_colconst[m0 + 2 * i + 1]) - 2.0f * d.y, 0.0f);
        if (sq0 < thresh) {
            int idx = atomicAdd(&g_ncand, 1);
            if (idx < CAND_CAP) g_cand[idx] = make_int2(b, m0 + 2 * i);
        }
        if (sq1 < thresh) {
            int idx = atomicAdd(&g_ncand, 1);
            if (idx < CAND_CAP) g_cand[idx] = make_int2(b, m0 + 2 * i + 1);
        }
    }
}

// ---------------- pass 3: exact fp32 rescore ----------------
__global__ void som_rescore(const float* __restrict__ x, const float* __restrict__ w) {
    int gwarp = (blockIdx.x * blockDim.x + threadIdx.x) >> 5;
    int lane = threadIdx.x & 31;
    int nwarps = (gridDim.x * blockDim.x) >> 5;
    int n = g_ncand;
    if (n > CAND_CAP) n = CAND_CAP;
    for (int i = gwarp; i < n; i += nwarps) {
        int b = g_cand[i].x, m = g_cand[i].y;
        const float* xr = x + (size_t)b * Dk;
        float dot = 0.f;
#pragma unroll 4
        for (int k = lane; k < Dk; k += 32)
            dot = fmaf(xr[k], __ldg(&w[(size_t)k * Mn + m]), dot);
#pragma unroll
        for (int o = 16; o; o >>= 1) dot += __shfl_down_sync(0xFFFFFFFFu, dot, o);
        if (lane == 0) {
            float sq = fmaxf(g_rowconst[b] + g_colconst[m] - 2.0f * dot, 0.0f);
            unsigned long long key =
                ((unsigned long long)__float_as_uint(sq) << 32) | (unsigned int)m;
            atomicMin(&g_best2[b], key);
        }
    }
}

// ---------------- finalize ----------------
__global__ void som_finalize(const float* __restrict__ loc, float* __restrict__ out) {
    __shared__ float ssum[256];
    int tid = threadIdx.x;
    float local = 0.f;
    for (int b = tid; b < Bn; b += 256) {
        unsigned long long v = g_best2[b];
        unsigned int m = (unsigned int)(v & 0xFFFFFFFFu);
        float sq = __uint_as_float((unsigned int)(v >> 32));
        out[b] = (float)m;
        out[Bn + 2 * b + 0] = loc[2 * m + 0];
        out[Bn + 2 * b + 1] = loc[2 * m + 1];
        local += sqrtf(sq);
    }
    ssum[tid] = local;
    __syncthreads();
    for (int s = 128; s; s >>= 1) {
        if (tid < s) ssum[tid] += ssum[tid + s];
        __syncthreads();
    }
    if (tid == 0) out[3 * Bn] = ssum[0] / (float)Bn;
}

// ---------------- launch ----------------
extern "C" void kernel_launch(void* const* d_in, const int* in_sizes, int n_in,
                              void* d_out, int out_size) {
    const float* x = (const float*)d_in[0];   // [B, D]
    const float* w = (const float*)d_in[1];   // [D, M]
    const float* loc = (const float*)d_in[2]; // [M, 2]
    float* out = (float*)d_out;

    static int configured = 0;
    if (!configured) {
        cudaFuncSetAttribute(som_mma, cudaFuncAttributeMaxDynamicSharedMemorySize, DYN_BYTES);
        configured = 1;
    }

    som_wconv<<<dim3(Mn / 4 / 256, DSLICE), 256>>>(w);
    som_xconv<<<Bn * 32 / 256, 256>>>(x);
    som_colreduce<<<Mn / 256, 256>>>();

    dim3 grid(Bn / BM, Mn / BN);   // x fastest: consecutive CTAs share the w panel (L2 reuse)
    som_mma<<<grid, 256, DYN_BYTES>>>();

    som_scan<<<Bn * NTILE / 8, 256>>>();
    som_rescore<<<256, 256>>>(x, w);

    som_finalize<<<1, 256>>>(loc, out);
}

// round 12
// speedup vs baseline: 1.1027x; 1.0017x over previous
#include <cuda_runtime.h>
#include <cuda_bf16.h>
#include <cuda_fp16.h>
#include <cstdint>

#define Bn 2048
#define Dk 1024
#define Mn 16384
#define EPSF 1e-6f

#define BM 128
#define BN 128
#define BK 64
#define NCH (Dk / BK)        // 16 chunks
#define NTILE (Mn / BN)      // 128 M-tiles

// padded pitches (bytes): A row = 64 bf16 = 128B -> 144; B row = 128 bf16 = 256B -> 272
#define A_PITCH 144
#define B_PITCH 272
#define A_HI 0
#define B_HI 18432           // 128*144
#define STAGE_SZ 35840       // + 64*272
#define NSTAGE 3
#define DOT_PITCH 136        // halves per smem dot row (272B, 16B-aligned)
#define DYN_BYTES (NSTAGE * STAGE_SZ)   // 107520 >= 128*136*2

#define DSLICE 8
#define E_MARGIN 3.5f
#define CAND_CAP (1 << 20)

// ---------------- device scratch ----------------
__device__ float g_rowconst[Bn];
__device__ float g_colconst[Mn];
__device__ float g_colpart[DSLICE * Mn];
__device__ unsigned long long g_best[Bn];    // approx (pass 1)
__device__ unsigned long long g_best2[Bn];   // exact (pass 3)
__device__ float g_tilemin[Bn * NTILE];      // approx sq min per (row, tile)
__device__ __nv_bfloat16 g_xhi[Bn * Dk];
__device__ __nv_bfloat16 g_whi[(size_t)Dk * Mn];
__device__ __half g_dot[(size_t)Bn * Mn];
__device__ int2 g_cand[CAND_CAP];
__device__ int g_ncand;

// ---------------- helpers ----------------
__device__ __forceinline__ uint32_t smem_u32(const void* p) {
    uint32_t a;
    asm("{ .reg .u64 t; cvta.to.shared.u64 t, %1; cvt.u32.u64 %0, t; }" : "=r"(a) : "l"(p));
    return a;
}
__device__ __forceinline__ void cp16(uint32_t s, const void* g) {
    asm volatile("cp.async.cg.shared.global [%0], [%1], 16;" :: "r"(s), "l"(g) : "memory");
}
__device__ __forceinline__ void cp_commit() { asm volatile("cp.async.commit_group;" ::: "memory"); }
__device__ __forceinline__ void cp_wait1()  { asm volatile("cp.async.wait_group 1;" ::: "memory"); }

__device__ __forceinline__ void ldsm_x4(uint32_t* r, uint32_t addr) {
    asm volatile("ldmatrix.sync.aligned.m8n8.x4.shared.b16 {%0,%1,%2,%3}, [%4];"
                 : "=r"(r[0]), "=r"(r[1]), "=r"(r[2]), "=r"(r[3]) : "r"(addr));
}
__device__ __forceinline__ void ldsm_x4_t(uint32_t* r, uint32_t addr) {
    asm volatile("ldmatrix.sync.aligned.m8n8.x4.trans.shared.b16 {%0,%1,%2,%3}, [%4];"
                 : "=r"(r[0]), "=r"(r[1]), "=r"(r[2]), "=r"(r[3]) : "r"(addr));
}
__device__ __forceinline__ void mma_bf16(float* c, const uint32_t* a, const uint32_t* b) {
    asm volatile(
        "mma.sync.aligned.m16n8k16.row.col.f32.bf16.bf16.f32 "
        "{%0,%1,%2,%3}, {%4,%5,%6,%7}, {%8,%9}, {%0,%1,%2,%3};"
        : "+f"(c[0]), "+f"(c[1]), "+f"(c[2]), "+f"(c[3])
        : "r"(a[0]), "r"(a[1]), "r"(a[2]), "r"(a[3]), "r"(b[0]), "r"(b[1]));
}

// ---------------- w convert + partial stats (float4 across m) ----------------
__global__ void som_wconv(const float* __restrict__ w) {
    int m4 = blockIdx.x * blockDim.x + threadIdx.x;    // 0..Mn/4-1
    int z = blockIdx.y;
    int d0 = z * (Dk / DSLICE);
    int m = m4 * 4;
    float4 s2 = make_float4(0.f, 0.f, 0.f, 0.f);
    float4 s1 = make_float4(0.f, 0.f, 0.f, 0.f);
#pragma unroll 4
    for (int i = 0; i < Dk / DSLICE; i++) {
        size_t idx = (size_t)(d0 + i) * Mn + m;
        float4 v = *(const float4*)(w + idx);
        s2.x = fmaf(v.x, v.x, s2.x); s1.x += v.x;
        s2.y = fmaf(v.y, v.y, s2.y); s1.y += v.y;
        s2.z = fmaf(v.z, v.z, s2.z); s1.z += v.z;
        s2.w = fmaf(v.w, v.w, s2.w); s1.w += v.w;
        __nv_bfloat16 h[4] = {__float2bfloat16(v.x), __float2bfloat16(v.y),
                              __float2bfloat16(v.z), __float2bfloat16(v.w)};
        *(uint2*)&g_whi[idx] = *(uint2*)h;
    }
    float4 r;
    r.x = s2.x - 2.0f * EPSF * s1.x;
    r.y = s2.y - 2.0f * EPSF * s1.y;
    r.z = s2.z - 2.0f * EPSF * s1.z;
    r.w = s2.w - 2.0f * EPSF * s1.w;
    *(float4*)&g_colpart[z * Mn + m] = r;
}

// colconst reduce + init best keys + candidate counter (merged)
__global__ void som_colreduce() {
    int m = blockIdx.x * blockDim.x + threadIdx.x;
    float s = 0.f;
#pragma unroll
    for (int z = 0; z < DSLICE; z++) s += g_colpart[z * Mn + m];
    g_colconst[m] = s;
    if (m < Bn) { g_best[m] = ~0ull; g_best2[m] = ~0ull; }
    if (m == 0) g_ncand = 0;
}

// ---------------- x convert + stats ----------------
__global__ void som_xconv(const float* __restrict__ x) {
    int gw = (blockIdx.x * blockDim.x + threadIdx.x) >> 5;
    int lane = threadIdx.x & 31;
    if (gw >= Bn) return;
    const float4* xr = (const float4*)(x + (size_t)gw * Dk);
    float s2 = 0.f, s1 = 0.f;
#pragma unroll
    for (int i = lane; i < Dk / 4; i += 32) {
        float4 v = xr[i];
        s1 += v.x + v.y + v.z + v.w;
        s2 = fmaf(v.x, v.x, s2); s2 = fmaf(v.y, v.y, s2);
        s2 = fmaf(v.z, v.z, s2); s2 = fmaf(v.w, v.w, s2);
        __nv_bfloat16 h[4] = {__float2bfloat16(v.x), __float2bfloat16(v.y),
                              __float2bfloat16(v.z), __float2bfloat16(v.w)};
        *(uint2*)&g_xhi[(size_t)gw * Dk + i * 4] = *(uint2*)h;
    }
#pragma unroll
    for (int o = 16; o; o >>= 1) {
        s1 += __shfl_down_sync(0xFFFFFFFFu, s1, o);
        s2 += __shfl_down_sync(0xFFFFFFFFu, s2, o);
    }
    if (lane == 0) g_rowconst[gw] = s2 + 2.0f * EPSF * s1 + (float)Dk * EPSF * EPSF;
}

// ---------------- pass 1: hi*hi GEMM + approx min + fp16 dot store ----------------
__global__ __launch_bounds__(256, 2) void som_mma(void) {
    extern __shared__ uint8_t dyn[];
    __shared__ float s_tmin[128][4];

    const int tid = threadIdx.x;
    const int lid = tid & 31;
    const int wid = tid >> 5;
    const int warp_m = wid >> 2;
    const int warp_n = wid & 3;
    const int bRow = blockIdx.x * BM;
    const int bCol = blockIdx.y * BN;

    float acc[4][4][4];
#pragma unroll
    for (int i = 0; i < 4; i++)
#pragma unroll
        for (int j = 0; j < 4; j++)
#pragma unroll
            for (int k = 0; k < 4; k++) acc[i][j][k] = 0.f;

    const uint32_t sb0 = smem_u32(dyn);

    // cp.async mapping, 4 x 16B each for A and B per stage per thread
    uint32_t a_soff[4], b_soff[4];
    size_t a_goff[4], b_goff[4];
#pragma unroll
    for (int i = 0; i < 4; i++) {
        int q = tid + i * 256;                 // 0..1023
        int ar = q >> 3, ak = q & 7;           // A: 128 rows x 8 chunks
        a_soff[i] = ar * A_PITCH + ak * 16;
        a_goff[i] = (size_t)(bRow + ar) * Dk + ak * 8;
        int br = q >> 4, bn = q & 15;          // B: 64 rows x 16 chunks
        b_soff[i] = br * B_PITCH + bn * 16;
        b_goff[i] = (size_t)br * Mn + bCol + bn * 8;
    }

    auto issue_stage = [&](int c) {
        const uint32_t sb = sb0 + (c % NSTAGE) * STAGE_SZ;
        const int k0 = c * BK;
#pragma unroll
        for (int i = 0; i < 4; i++) {
            cp16(sb + A_HI + a_soff[i], g_xhi + a_goff[i] + k0);
            cp16(sb + B_HI + b_soff[i], g_whi + b_goff[i] + (size_t)k0 * Mn);
        }
    };

    const uint32_t a_ld = (warp_m * 64 + (lid & 15)) * A_PITCH + (lid >> 4) * 16;
    const uint32_t b_ld = (((lid >> 3) & 1) * 8 + (lid & 7)) * B_PITCH +
                          warp_n * 64 + ((lid >> 3) >> 1) * 16;

    issue_stage(0); cp_commit();
    issue_stage(1); cp_commit();

#pragma unroll 1
    for (int c = 0; c < NCH; c++) {
        cp_wait1();
        __syncthreads();
        const uint32_t sb = sb0 + (c % NSTAGE) * STAGE_SZ;

#pragma unroll
        for (int ks = 0; ks < 4; ks++) {
            uint32_t bh[2][4], af[4][4];
#pragma unroll
            for (int g = 0; g < 2; g++)
                ldsm_x4_t(bh[g], sb + B_HI + b_ld + ks * 16 * B_PITCH + g * 32);
#pragma unroll
            for (int mt = 0; mt < 4; mt++)
                ldsm_x4(af[mt], sb + A_HI + a_ld + mt * 16 * A_PITCH + ks * 32);
#pragma unroll
            for (int mt = 0; mt < 4; mt++)
#pragma unroll
                for (int nt = 0; nt < 4; nt++)
                    mma_bf16(acc[mt][nt], af[mt], &bh[nt >> 1][(nt & 1) * 2]);
        }

        if (c + 2 < NCH) issue_stage(c + 2);
        cp_commit();
    }

    // ---- epilogue ----
    float ccv[4][2];
    const int cbase = bCol + warp_n * 32 + (lid & 3) * 2;
#pragma unroll
    for (int nt = 0; nt < 4; nt++) {
        ccv[nt][0] = __ldg(&g_colconst[cbase + nt * 8]);
        ccv[nt][1] = __ldg(&g_colconst[cbase + nt * 8 + 1]);
    }

    __syncthreads();   // stage buffers dead; reuse as fp16 dot tile [128][DOT_PITCH]
    __half* sdot = (__half*)dyn;

#pragma unroll
    for (int mt = 0; mt < 4; mt++) {
#pragma unroll
        for (int half = 0; half < 2; half++) {
            const int rloc = warp_m * 64 + mt * 16 + (lid >> 2) + half * 8;
            const int row = bRow + rloc;
            const float rc = __ldg(&g_rowconst[row]);
            unsigned long long best = ~0ull;
#pragma unroll
            for (int nt = 0; nt < 4; nt++) {
                __half2 hp;
#pragma unroll
                for (int q = 0; q < 2; q++) {
                    float dotf = acc[mt][nt][half * 2 + q];
                    __half dh = __float2half(dotf);
                    ((__half*)&hp)[q] = dh;
                    float sq = fmaxf(rc + ccv[nt][q] - 2.0f * __half2float(dh), 0.0f);
                    int m = cbase + nt * 8 + q;
                    unsigned long long key =
                        ((unsigned long long)__float_as_uint(sq) << 32) | (unsigned int)m;
                    best = (key < best) ? key : best;
                }
                *(__half2*)&sdot[rloc * DOT_PITCH + warp_n * 32 + nt * 8 + (lid & 3) * 2] = hp;
            }
            unsigned long long o1 = __shfl_xor_sync(0xFFFFFFFFu, best, 1);
            best = (o1 < best) ? o1 : best;
            unsigned long long o2 = __shfl_xor_sync(0xFFFFFFFFu, best, 2);
            best = (o2 < best) ? o2 : best;
            if ((lid & 3) == 0) {
                s_tmin[rloc][warp_n] = __uint_as_float((unsigned int)(best >> 32));
                atomicMin(&g_best[row], best);
            }
        }
    }

    __syncthreads();
    // per-row tile min over the 4 warp_n columns -> g_tilemin
    if (tid < 128) {
        float t0 = fminf(s_tmin[tid][0], s_tmin[tid][1]);
        float t1 = fminf(s_tmin[tid][2], s_tmin[tid][3]);
        g_tilemin[(bRow + tid) * NTILE + blockIdx.y] = fminf(t0, t1);
    }
    // coalesced store of the 128x128 fp16 tile to g_dot
#pragma unroll
    for (int i = 0; i < 8; i++) {
        int chunk = tid + i * 256;        // 0..2047
        int r = chunk >> 4;
        int o = (chunk & 15) * 8;
        uint4 v = *(uint4*)&sdot[r * DOT_PITCH + o];
        *(uint4*)&g_dot[(size_t)(bRow + r) * Mn + bCol + o] = v;
    }
}

// ---------------- pass 2: tile-screened candidate scan ----------------
// one warp per (row, tile); skip tile unless its approx min beats thresh
__global__ void som_scan(void) {
    int gwarp = blockIdx.x * 8 + (threadIdx.x >> 5);   // 0 .. Bn*NTILE-1
    int lane = threadIdx.x & 31;
    int b = gwarp >> 7;          // / NTILE
    int tile = gwarp & (NTILE - 1);
    float thresh = __uint_as_float((unsigned int)(g_best[b] >> 32)) + E_MARGIN;
    if (g_tilemin[b * NTILE + tile] >= thresh) return;

    float rc = g_rowconst[b];
    int m0 = tile * BN + lane * 4;
    uint2 dv = *(const uint2*)&g_dot[(size_t)b * Mn + m0];
    const __half2* dh = (const __half2*)&dv;
#pragma unroll
    for (int i = 0; i < 2; i++) {
        float2 d = __half22float2(dh[i]);
        float sq0 = fmaxf(rc + __ldg(&g_colconst[m0 + 2 * i])     - 2.0f * d.x, 0.0f);
        float sq1 = fmaxf(rc + __ldg(&g_colconst[m0 + 2 * i + 1]) - 2.0f * d.y, 0.0f);
        if (sq0 < thresh) {
            int idx = atomicAdd(&g_ncand, 1);
            if (idx < CAND_CAP) g_cand[idx] = make_int2(b, m0 + 2 * i);
        }
        if (sq1 < thresh) {
            int idx = atomicAdd(&g_ncand, 1);
            if (idx < CAND_CAP) g_cand[idx] = make_int2(b, m0 + 2 * i + 1);
        }
    }
}

// ---------------- pass 3: exact fp32 rescore ----------------
__global__ void som_rescore(const float* __restrict__ x, const float* __restrict__ w) {
    int gwarp = (blockIdx.x * blockDim.x + threadIdx.x) >> 5;
    int lane = threadIdx.x & 31;
    int nwarps = (gridDim.x * blockDim.x) >> 5;
    int n = g_ncand;
    if (n > CAND_CAP) n = CAND_CAP;
    for (int i = gwarp; i < n; i += nwarps) {
        int b = g_cand[i].x, m = g_cand[i].y;
        const float* xr = x + (size_t)b * Dk;
        float dot = 0.f;
#pragma unroll 4
        for (int k = lane; k < Dk; k += 32)
            dot = fmaf(xr[k], __ldg(&w[(size_t)k * Mn + m]), dot);
#pragma unroll
        for (int o = 16; o; o >>= 1) dot += __shfl_down_sync(0xFFFFFFFFu, dot, o);
        if (lane == 0) {
            float sq = fmaxf(g_rowconst[b] + g_colconst[m] - 2.0f * dot, 0.0f);
            unsigned long long key =
                ((unsigned long long)__float_as_uint(sq) << 32) | (unsigned int)m;
            atomicMin(&g_best2[b], key);
        }
    }
}

// ---------------- finalize ----------------
__global__ void som_finalize(const float* __restrict__ loc, float* __restrict__ out) {
    __shared__ float ssum[256];
    int tid = threadIdx.x;
    float local = 0.f;
    for (int b = tid; b < Bn; b += 256) {
        unsigned long long v = g_best2[b];
        unsigned int m = (unsigned int)(v & 0xFFFFFFFFu);
        float sq = __uint_as_float((unsigned int)(v >> 32));
        out[b] = (float)m;
        out[Bn + 2 * b + 0] = loc[2 * m + 0];
        out[Bn + 2 * b + 1] = loc[2 * m + 1];
        local += sqrtf(sq);
    }
    ssum[tid] = local;
    __syncthreads();
    for (int s = 128; s; s >>= 1) {
        if (tid < s) ssum[tid] += ssum[tid + s];
        __syncthreads();
    }
    if (tid == 0) out[3 * Bn] = ssum[0] / (float)Bn;
}

// ---------------- launch ----------------
extern "C" void kernel_launch(void* const* d_in, const int* in_sizes, int n_in,
                              void* d_out, int out_size) {
    const float* x = (const float*)d_in[0];   // [B, D]
    const float* w = (const float*)d_in[1];   // [D, M]
    const float* loc = (const float*)d_in[2]; // [M, 2]
    float* out = (float*)d_out;

    static int configured = 0;
    if (!configured) {
        cudaFuncSetAttribute(som_mma, cudaFuncAttributeMaxDynamicSharedMemorySize, DYN_BYTES);
        configured = 1;
    }

    som_wconv<<<dim3(Mn / 4 / 256, DSLICE), 256>>>(w);
    som_xconv<<<Bn * 32 / 256, 256>>>(x);
    som_colreduce<<<Mn / 256, 256>>>();

    dim3 grid(Bn / BM, Mn / BN);   // x fastest: consecutive CTAs share the w panel (L2 reuse)
    som_mma<<<grid, 256, DYN_BYTES>>>();

    som_scan<<<Bn * NTILE / 8, 256>>>();
    som_rescore<<<256, 256>>>(x, w);

    som_finalize<<<1, 256>>>(loc, out);
}